// round 15
// baseline (speedup 1.0000x reference)
#include <cuda_runtime.h>
#include <cuda_fp16.h>
#include <math.h>
#include <stdint.h>

#define BB   8
#define CCH  256
#define HH   96
#define WW   96
#define HWN  (HH*WW)        // 9216
#define OC   256
#define KF   4

// Scratch
__device__ __half g_projh[(size_t)BB * HWN * OC];        // [b][p][o] pixel-major, fp16
__device__ int    g_sidx[BB * HWN * 16];                 // compacted gather offsets
__device__ float  g_swt [BB * HWN * 16];                 // compacted fused weights
__device__ int    g_scnt[BB * HWN];                      // per-pixel tap count (mult of 4)
__device__ __half g_wh[OC * CCH];                        // fp16(Wc) [o][c]
__device__ __half g_xh[(size_t)BB * CCH * HWN];          // fp16(x) [b][c][p]
__device__ float  g_part[4 * 12 * BB * HWN];             // partial dots [qtr*12+m][b][p]

// ---------------------------------------------------------------------------
union P2 { float2 f; unsigned long long u; };
__device__ __forceinline__ void fma2(unsigned long long& d,
                                     unsigned long long a,
                                     unsigned long long b) {
    asm("fma.rn.f32x2 %0, %1, %2, %0;" : "+l"(d) : "l"(a), "l"(b));
}

__device__ __forceinline__ uint32_t smem_u32(const void* p) {
    uint32_t a;
    asm("{ .reg .u64 t; cvta.to.shared.u64 t, %1; cvt.u32.u64 %0, t; }" : "=r"(a) : "l"(p));
    return a;
}
#define CPA16(dst, src) asm volatile("cp.async.cg.shared.global [%0], [%1], 16;" :: "r"(dst), "l"(src) : "memory")
#define CPA_COMMIT()    asm volatile("cp.async.commit_group;" ::: "memory")
#define CPA_WAIT2()     asm volatile("cp.async.wait_group 2;" ::: "memory")

#define LDSM_X4(r, a) \
    asm volatile("ldmatrix.sync.aligned.m8n8.x4.shared.b16 {%0,%1,%2,%3}, [%4];" \
        : "=r"((r)[0]), "=r"((r)[1]), "=r"((r)[2]), "=r"((r)[3]) : "r"(a))
#define LDSM_X4_T(r, a) \
    asm volatile("ldmatrix.sync.aligned.m8n8.x4.trans.shared.b16 {%0,%1,%2,%3}, [%4];" \
        : "=r"((r)[0]), "=r"((r)[1]), "=r"((r)[2]), "=r"((r)[3]) : "r"(a))

__device__ __forceinline__ void mma16816(float* c, const uint32_t* a, const uint32_t* b) {
    asm volatile("mma.sync.aligned.m16n8k16.row.col.f32.f16.f16.f32 "
                 "{%0,%1,%2,%3}, {%4,%5,%6,%7}, {%8,%9}, {%0,%1,%2,%3};"
                 : "+f"(c[0]), "+f"(c[1]), "+f"(c[2]), "+f"(c[3])
                 : "r"(a[0]), "r"(a[1]), "r"(a[2]), "r"(a[3]), "r"(b[0]), "r"(b[1]));
}

// ---------------------------------------------------------------------------
// Kernel 1a (dots): grid (72, 8, 4). Block (bx,b,qtr) handles 64 channels of
// 128 pixels: partial 12-dots + fp16 conversion of that channel quarter.
__global__ __launch_bounds__(128) void DFMAtt_dots(
        const float* __restrict__ x,    const float* __restrict__ Wc,
        const float* __restrict__ Woff, const float* __restrict__ Wwt) {
    __shared__ float2 sW2[12][32];
    int tid = threadIdx.x;
    int qtr = blockIdx.z;
    int b   = blockIdx.y;

    if (qtr == 0) {                       // folded wprep on z==0 slice
        int blk = b * 72 + blockIdx.x;
        if (blk < 512) {
            int i = blk * 128 + tid;
            g_wh[i] = __float2half_rn(Wc[i]);
        }
    }

    for (int i = tid; i < 12 * 32; i += 128) {
        int m = i >> 5, cc = i & 31;
        int c2 = qtr * 32 + cc;
        const float* src = (m < 8) ? (Woff + m * CCH) : (Wwt + (m - 8) * CCH);
        sW2[m][cc] = *(const float2*)(src + c2 * 2);
    }
    __syncthreads();

    int p = blockIdx.x * 128 + tid;
    const float* xp = x    + ((size_t)(b * CCH + qtr * 64)) * HWN + p;
    __half*      xh = g_xh + ((size_t)(b * CCH + qtr * 64)) * HWN + p;

    unsigned long long acc2[12];
    #pragma unroll
    for (int m = 0; m < 12; m++) acc2[m] = 0ull;

    #pragma unroll
    for (int cb = 0; cb < 64; cb += 16) {
        float v[16];
        #pragma unroll
        for (int j = 0; j < 16; j++)
            v[j] = xp[(size_t)(cb + j) * HWN];
        #pragma unroll
        for (int j = 0; j < 16; j++)
            xh[(size_t)(cb + j) * HWN] = __float2half_rn(v[j]);
        #pragma unroll
        for (int q = 0; q < 8; q++) {
            P2 xv; xv.f = make_float2(v[q * 2], v[q * 2 + 1]);
            int c2 = (cb >> 1) + q;
            #pragma unroll
            for (int m = 0; m < 12; m++) {
                P2 w; w.f = sW2[m][c2];
                fma2(acc2[m], xv.u, w.u);
            }
        }
    }

    #pragma unroll
    for (int m = 0; m < 12; m++) {
        P2 t; t.u = acc2[m];
        g_part[((size_t)(qtr * 12 + m) * BB + b) * HWN + p] = t.f.x + t.f.y;
    }
}

// ---------------------------------------------------------------------------
// Kernel 1b (flow epilogue): sum 4 partials -> softmax -> dedupe -> compact.
// cnt padded to a multiple of 4 for the sample kernel's unroll-4 gather.
__global__ __launch_bounds__(128) void DFMAtt_flowepi(
        const float* __restrict__ boff, const float* __restrict__ bwt) {
    int tid = threadIdx.x;
    int b = blockIdx.y;
    int p = blockIdx.x * 128 + tid;

    float acc[12];
    #pragma unroll
    for (int m = 0; m < 12; m++) {
        float q0 = g_part[((size_t)(0 * 12 + m) * BB + b) * HWN + p];
        float q1 = g_part[((size_t)(1 * 12 + m) * BB + b) * HWN + p];
        float q2 = g_part[((size_t)(2 * 12 + m) * BB + b) * HWN + p];
        float q3 = g_part[((size_t)(3 * 12 + m) * BB + b) * HWN + p];
        acc[m] = (q0 + q1) + (q2 + q3);
    }

    float lg[KF];
    #pragma unroll
    for (int k = 0; k < KF; k++) lg[k] = acc[8 + k] + bwt[k];
    float mx = fmaxf(fmaxf(lg[0], lg[1]), fmaxf(lg[2], lg[3]));
    float e[KF], ssum = 0.f;
    #pragma unroll
    for (int k = 0; k < KF; k++) { e[k] = expf(lg[k] - mx); ssum += e[k]; }
    float inv = 1.f / ssum;

    int px = p % WW, py = p / WW;

    int   idxr[16];
    float wtr [16];
    bool  keep[16];
    #pragma unroll
    for (int k = 0; k < KF; k++) {
        float wk = e[k] * inv;
        float fx = acc[k * 2 + 0] + boff[k * 2 + 0];
        float fy = acc[k * 2 + 1] + boff[k * 2 + 1];
        float vx = 2.0f * ((float)px + fx) / (float)(WW - 1) - 1.0f;
        float vy = 2.0f * ((float)py + fy) / (float)(HH - 1) - 1.0f;
        float ix = (vx + 1.0f) * ((float)WW * 0.5f) - 0.5f;
        float iy = (vy + 1.0f) * ((float)HH * 0.5f) - 0.5f;
        float x0f = floorf(ix), y0f = floorf(iy);
        float wx1 = ix - x0f, wx0 = 1.0f - wx1;
        float wy1 = iy - y0f, wy0 = 1.0f - wy1;
        int x0 = (int)x0f, y0 = (int)y0f;
        #pragma unroll
        for (int t = 0; t < 4; t++) {
            int xi = x0 + (t & 1);
            int yi = y0 + (t >> 1);
            float wt = ((t & 1) ? wx1 : wx0) * ((t >> 1) ? wy1 : wy0);
            bool valid = (xi >= 0) && (xi < WW) && (yi >= 0) && (yi < HH);
            int xc = min(max(xi, 0), WW - 1);
            int yc = min(max(yi, 0), HH - 1);
            int q = k * 4 + t;
            idxr[q] = (yc * WW + xc) * OC;
            wtr [q] = valid ? (wk * wt) : 0.0f;
            keep[q] = true;
        }
    }

    #pragma unroll
    for (int j = 1; j < 16; j++)
        #pragma unroll
        for (int i = 0; i < j; i++)
            if (keep[j] && keep[i] && idxr[j] == idxr[i]) {
                wtr[i] += wtr[j];
                keep[j] = false;
            }

    int base = (b * HWN + p) * 16;
    int cnt = 0;
    #pragma unroll
    for (int t = 0; t < 16; t++)
        if (keep[t] && wtr[t] != 0.0f) {
            g_sidx[base + cnt] = idxr[t];
            g_swt [base + cnt] = wtr[t];
            cnt++;
        }
    while (cnt & 3) {                    // pad to multiple of 4
        g_sidx[base + cnt] = 0;
        g_swt [base + cnt] = 0.0f;
        cnt++;
    }
    g_scnt[b * HWN + p] = cnt;
}

// ---------------------------------------------------------------------------
// Kernel 2: mma.sync fp16 GEMM, CONTINUOUS 4-stage cp.async ring spanning
// tile boundaries (prefetch 3 ahead, wait_group 2). Persistent 296 CTAs.
#define BS_STRIDE 264
#define AS_STRIDE 136
#define B_MAT_BYTES (128 * BS_STRIDE * 2)   // 67584
#define A_STG_BYTES (32 * AS_STRIDE * 2)    // 8704
#define OFF_A B_MAT_BYTES
#define SMEM_TOT (OFF_A + 4 * A_STG_BYTES)  // 102400 -> 2 CTAs/SM

__device__ __forceinline__ void prefA(uint32_t smA, int st, int b, int ck, int prow, int tid) {
    #pragma unroll
    for (int it = 0; it < 2; it++) {
        int idx = tid + it * 256;
        int r = idx >> 4, j = idx & 15;
        const __half* src = g_xh + ((size_t)(b * CCH + ck * 32 + r)) * HWN + prow + j * 8;
        uint32_t dst = smA + (uint32_t)st * A_STG_BYTES + r * (AS_STRIDE * 2) + j * 16;
        CPA16(dst, src);
    }
}

__global__ __launch_bounds__(256, 2) void DFMAtt_gemm_mma(const float* __restrict__ bc) {
    extern __shared__ unsigned char sm[];
    uint32_t sb = smem_u32(sm);
    int tid = threadIdx.x, wid = tid >> 5, lane = tid & 31;
    int nh = (blockIdx.x >= 148) ? 1 : 0;
    int local = blockIdx.x % 148;

    for (int idx = tid; idx < 128 * 32; idx += 256) {
        int r = idx >> 5, j = idx & 31;
        const __half* wsrc = g_wh + (size_t)(nh * 128 + r) * CCH + j * 8;
        *(uint4*)(sm + r * (BS_STRIDE * 2) + j * 16) = *(const uint4*)wsrc;
    }

    int wm = wid >> 2, wn = wid & 3;
    int p0w = wm * 64, o0w = wn * 32;
    int grp = lane >> 3, lr = lane & 7;

    int a_dc = ((grp >> 1) << 3) + lr;
    int a_dp = (grp & 1) << 3;
    uint32_t aoff[4];
    #pragma unroll
    for (int i = 0; i < 4; i++)
        aoff[i] = (uint32_t)(a_dc * (AS_STRIDE * 2) + (p0w + i * 16 + a_dp) * 2);
    int b_dr = ((grp >> 1) << 3) + lr;
    int b_dk = (grp & 1) << 4;
    uint32_t boff[2];
    #pragma unroll
    for (int t = 0; t < 2; t++)
        boff[t] = (uint32_t)((o0w + t * 16 + b_dr) * (BS_STRIDE * 2) + b_dk);

    uint32_t smA = sb + OFF_A;

    int row = lane >> 2, col2 = (lane & 3) * 2;
    float2 biasv[4];
    #pragma unroll
    for (int nt = 0; nt < 4; nt++)
        biasv[nt] = *(const float2*)&bc[nh * 128 + o0w + nt * 8 + col2];

    int T = (576 - local + 147) / 148;
    int bb = local / 72, pr = local % 72;

    // prime the ring: chunks 0,1,2 of first tile
    prefA(smA, 0, bb, 0, pr * 128, tid); CPA_COMMIT();
    prefA(smA, 1, bb, 1, pr * 128, tid); CPA_COMMIT();
    prefA(smA, 2, bb, 2, pr * 128, tid); CPA_COMMIT();

    int g = 0;
    for (int ti = 0; ti < T; ti++) {
        int b = bb, prow = pr * 128;
        int bbN = bb + 2, prN = pr + 4;
        if (prN >= 72) { prN -= 72; bbN++; }

        float acc[4][4][4];
        #pragma unroll
        for (int i = 0; i < 4; i++)
            #pragma unroll
            for (int nt = 0; nt < 4; nt++)
                #pragma unroll
                for (int q = 0; q < 4; q++) acc[i][nt][q] = 0.f;

        #pragma unroll 1
        for (int ck = 0; ck < 8; ck++, g++) {
            CPA_WAIT2();
            __syncthreads();
            uint32_t Ab = smA + (uint32_t)(g & 3) * A_STG_BYTES;

            #pragma unroll
            for (int ks = 0; ks < 2; ks++) {
                uint32_t ac  = (uint32_t)(ks * 16 * (AS_STRIDE * 2));
                uint32_t bcf = (uint32_t)((ck * 32 + ks * 16) * 2);
                uint32_t ah[4][4];
                #pragma unroll
                for (int i = 0; i < 4; i++) LDSM_X4_T(ah[i], Ab + ac + aoff[i]);
                uint32_t bh[2][4];
                #pragma unroll
                for (int t = 0; t < 2; t++) LDSM_X4(bh[t], sb + bcf + boff[t]);
                #pragma unroll
                for (int i = 0; i < 4; i++)
                    #pragma unroll
                    for (int nt = 0; nt < 4; nt++)
                        mma16816(acc[i][nt], ah[i], &bh[nt >> 1][(nt & 1) * 2]);
            }

            // prefetch chunk g+3 (possibly next tile's chunk ck-5)
            int gp = g + 3;
            if (gp < T * 8) {
                if (ck < 5) prefA(smA, gp & 3, b,   (ck + 3),     prow,      tid);
                else        prefA(smA, gp & 3, bbN, (ck + 3) & 7, prN * 128, tid);
            }
            CPA_COMMIT();
        }

        #pragma unroll
        for (int i = 0; i < 4; i++) {
            int p = prow + p0w + i * 16 + row;
            __half* dst0 = g_projh + ((size_t)b * HWN + p) * OC + nh * 128 + o0w + col2;
            #pragma unroll
            for (int nt = 0; nt < 4; nt++) {
                __half2 v0 = __floats2half2_rn(acc[i][nt][0] + biasv[nt].x,
                                               acc[i][nt][1] + biasv[nt].y);
                __half2 v1 = __floats2half2_rn(acc[i][nt][2] + biasv[nt].x,
                                               acc[i][nt][3] + biasv[nt].y);
                *(__half2*)(dst0 + nt * 8)          = v0;
                *(__half2*)(dst0 + nt * 8 + 8 * OC) = v1;
            }
        }
        bb = bbN; pr = prN;
    }
}

// ---------------------------------------------------------------------------
// Kernel 3: out[b][o][p] = sum_{i<cnt} w_i * projh[b][idx_i][o]
// 32 lanes x uint4; unroll-4 gather (4 independent LDG.128 per iteration).
__global__ __launch_bounds__(256) void DFMAtt_sample(float* __restrict__ out) {
    __shared__ float s_acc[32][257];
    __shared__ int   s_idx[32][16];
    __shared__ float s_wt [32][16];
    __shared__ int   s_cnt[32];

    int b  = blockIdx.y;
    int p0 = blockIdx.x * 32;
    int tid = threadIdx.x;

    {
        const int*   gi = g_sidx + (b * HWN + p0) * 16;
        const float* gw = g_swt  + (b * HWN + p0) * 16;
        for (int i = tid; i < 512; i += 256) {
            s_idx[i >> 4][i & 15] = gi[i];
            s_wt [i >> 4][i & 15] = gw[i];
        }
        if (tid < 32) s_cnt[tid] = g_scnt[b * HWN + p0 + tid];
    }
    __syncthreads();

    const __half* projb = g_projh + (size_t)b * HWN * OC;
    int lane = tid & 31;
    int pg   = tid >> 5;

    #pragma unroll 1
    for (int s = 0; s < 4; s++) {
        int pi = s * 8 + pg;
        int cnt = s_cnt[pi];
        const __half* pb = projb + lane * 8;
        float f0 = 0.f, f1 = 0.f, f2 = 0.f, f3 = 0.f;
        float f4 = 0.f, f5 = 0.f, f6 = 0.f, f7 = 0.f;
        #pragma unroll 1
        for (int i = 0; i < cnt; i += 4) {
            float w0 = s_wt[pi][i];
            float w1 = s_wt[pi][i + 1];
            float w2 = s_wt[pi][i + 2];
            float w3 = s_wt[pi][i + 3];
            uint4 r0 = *(const uint4*)(pb + s_idx[pi][i]);
            uint4 r1 = *(const uint4*)(pb + s_idx[pi][i + 1]);
            uint4 r2 = *(const uint4*)(pb + s_idx[pi][i + 2]);
            uint4 r3 = *(const uint4*)(pb + s_idx[pi][i + 3]);
            {
                float2 a0 = __half22float2(*(__half2*)&r0.x);
                float2 a1 = __half22float2(*(__half2*)&r0.y);
                float2 a2 = __half22float2(*(__half2*)&r0.z);
                float2 a3 = __half22float2(*(__half2*)&r0.w);
                f0 = fmaf(w0, a0.x, f0); f1 = fmaf(w0, a0.y, f1);
                f2 = fmaf(w0, a1.x, f2); f3 = fmaf(w0, a1.y, f3);
                f4 = fmaf(w0, a2.x, f4); f5 = fmaf(w0, a2.y, f5);
                f6 = fmaf(w0, a3.x, f6); f7 = fmaf(w0, a3.y, f7);
            }
            {
                float2 a0 = __half22float2(*(__half2*)&r1.x);
                float2 a1 = __half22float2(*(__half2*)&r1.y);
                float2 a2 = __half22float2(*(__half2*)&r1.z);
                float2 a3 = __half22float2(*(__half2*)&r1.w);
                f0 = fmaf(w1, a0.x, f0); f1 = fmaf(w1, a0.y, f1);
                f2 = fmaf(w1, a1.x, f2); f3 = fmaf(w1, a1.y, f3);
                f4 = fmaf(w1, a2.x, f4); f5 = fmaf(w1, a2.y, f5);
                f6 = fmaf(w1, a3.x, f6); f7 = fmaf(w1, a3.y, f7);
            }
            {
                float2 a0 = __half22float2(*(__half2*)&r2.x);
                float2 a1 = __half22float2(*(__half2*)&r2.y);
                float2 a2 = __half22float2(*(__half2*)&r2.z);
                float2 a3 = __half22float2(*(__half2*)&r2.w);
                f0 = fmaf(w2, a0.x, f0); f1 = fmaf(w2, a0.y, f1);
                f2 = fmaf(w2, a1.x, f2); f3 = fmaf(w2, a1.y, f3);
                f4 = fmaf(w2, a2.x, f4); f5 = fmaf(w2, a2.y, f5);
                f6 = fmaf(w2, a3.x, f6); f7 = fmaf(w2, a3.y, f7);
            }
            {
                float2 a0 = __half22float2(*(__half2*)&r3.x);
                float2 a1 = __half22float2(*(__half2*)&r3.y);
                float2 a2 = __half22float2(*(__half2*)&r3.z);
                float2 a3 = __half22float2(*(__half2*)&r3.w);
                f0 = fmaf(w3, a0.x, f0); f1 = fmaf(w3, a0.y, f1);
                f2 = fmaf(w3, a1.x, f2); f3 = fmaf(w3, a1.y, f3);
                f4 = fmaf(w3, a2.x, f4); f5 = fmaf(w3, a2.y, f5);
                f6 = fmaf(w3, a3.x, f6); f7 = fmaf(w3, a3.y, f7);
            }
        }
        float* sa = &s_acc[pi][lane * 8];
        sa[0] = f0; sa[1] = f1; sa[2] = f2; sa[3] = f3;
        sa[4] = f4; sa[5] = f5; sa[6] = f6; sa[7] = f7;
    }
    __syncthreads();

    float* ob = out + (size_t)b * OC * HWN + p0;
    int orow = tid >> 5;
    int pi   = tid & 31;
    #pragma unroll 1
    for (int j = 0; j < 32; j++) {
        int o = orow + j * 8;
        ob[(size_t)o * HWN + pi] = s_acc[pi][o];
    }
}

// ---------------------------------------------------------------------------
extern "C" void kernel_launch(void* const* d_in, const int* in_sizes, int n_in,
                              void* d_out, int out_size) {
    const float* x    = (const float*)d_in[0];
    const float* Wc   = (const float*)d_in[1];
    const float* bc   = (const float*)d_in[2];
    const float* Woff = (const float*)d_in[3];
    const float* boff = (const float*)d_in[4];
    const float* Wwt  = (const float*)d_in[5];
    const float* bwt  = (const float*)d_in[6];
    float* out = (float*)d_out;

    cudaFuncSetAttribute(DFMAtt_gemm_mma,
                         cudaFuncAttributeMaxDynamicSharedMemorySize, SMEM_TOT);

    dim3 gd(72, BB, 4);
    DFMAtt_dots<<<gd, 128>>>(x, Wc, Woff, Wwt);

    dim3 ge(72, BB);
    DFMAtt_flowepi<<<ge, 128>>>(boff, bwt);

    DFMAtt_gemm_mma<<<296, 256, SMEM_TOT>>>(bc);

    dim3 gs(HWN / 32, BB);
    DFMAtt_sample<<<gs, 256>>>(out);
}

// round 16
// speedup vs baseline: 1.1193x; 1.1193x over previous
#include <cuda_runtime.h>
#include <cuda_fp16.h>
#include <math.h>
#include <stdint.h>

#define BB   8
#define CCH  256
#define HH   96
#define WW   96
#define HWN  (HH*WW)        // 9216
#define OC   256
#define KF   4

// Scratch
__device__ __half g_projh[(size_t)BB * HWN * OC];        // [b][p][o] pixel-major, fp16
__device__ int    g_sidx[BB * HWN * 16];                 // compacted gather offsets
__device__ float  g_swt [BB * HWN * 16];                 // compacted fused weights
__device__ int    g_scnt[BB * HWN];                      // per-pixel tap count (even)
__device__ __half g_wh[OC * CCH];                        // fp16(Wc) [o][c]
__device__ __half g_xh[(size_t)BB * CCH * HWN];          // fp16(x) [b][c][p]
__device__ float  g_part[4 * 12 * BB * HWN];             // partial dots [qtr*12+m][b][p]

// ---------------------------------------------------------------------------
union P2 { float2 f; unsigned long long u; };
__device__ __forceinline__ void fma2(unsigned long long& d,
                                     unsigned long long a,
                                     unsigned long long b) {
    asm("fma.rn.f32x2 %0, %1, %2, %0;" : "+l"(d) : "l"(a), "l"(b));
}

__device__ __forceinline__ uint32_t smem_u32(const void* p) {
    uint32_t a;
    asm("{ .reg .u64 t; cvta.to.shared.u64 t, %1; cvt.u32.u64 %0, t; }" : "=r"(a) : "l"(p));
    return a;
}
#define CPA16(dst, src) asm volatile("cp.async.cg.shared.global [%0], [%1], 16;" :: "r"(dst), "l"(src) : "memory")
#define CPA_COMMIT()    asm volatile("cp.async.commit_group;" ::: "memory")
#define CPA_WAIT2()     asm volatile("cp.async.wait_group 2;" ::: "memory")

#define LDSM_X4(r, a) \
    asm volatile("ldmatrix.sync.aligned.m8n8.x4.shared.b16 {%0,%1,%2,%3}, [%4];" \
        : "=r"((r)[0]), "=r"((r)[1]), "=r"((r)[2]), "=r"((r)[3]) : "r"(a))
#define LDSM_X4_T(r, a) \
    asm volatile("ldmatrix.sync.aligned.m8n8.x4.trans.shared.b16 {%0,%1,%2,%3}, [%4];" \
        : "=r"((r)[0]), "=r"((r)[1]), "=r"((r)[2]), "=r"((r)[3]) : "r"(a))

__device__ __forceinline__ void mma16816(float* c, const uint32_t* a, const uint32_t* b) {
    asm volatile("mma.sync.aligned.m16n8k16.row.col.f32.f16.f16.f32 "
                 "{%0,%1,%2,%3}, {%4,%5,%6,%7}, {%8,%9}, {%0,%1,%2,%3};"
                 : "+f"(c[0]), "+f"(c[1]), "+f"(c[2]), "+f"(c[3])
                 : "r"(a[0]), "r"(a[1]), "r"(a[2]), "r"(a[3]), "r"(b[0]), "r"(b[1]));
}

// ---------------------------------------------------------------------------
// Kernel 1a (dots): grid (72, 8, 4). Block (bx,b,qtr) handles 64 channels of
// 128 pixels: partial 12-dots + fp16 conversion of that channel quarter.
__global__ __launch_bounds__(128) void DFMAtt_dots(
        const float* __restrict__ x,    const float* __restrict__ Wc,
        const float* __restrict__ Woff, const float* __restrict__ Wwt) {
    __shared__ float2 sW2[12][32];
    int tid = threadIdx.x;
    int qtr = blockIdx.z;
    int b   = blockIdx.y;

    if (qtr == 0) {                       // folded wprep on z==0 slice
        int blk = b * 72 + blockIdx.x;
        if (blk < 512) {
            int i = blk * 128 + tid;
            g_wh[i] = __float2half_rn(Wc[i]);
        }
    }

    for (int i = tid; i < 12 * 32; i += 128) {
        int m = i >> 5, cc = i & 31;
        int c2 = qtr * 32 + cc;
        const float* src = (m < 8) ? (Woff + m * CCH) : (Wwt + (m - 8) * CCH);
        sW2[m][cc] = *(const float2*)(src + c2 * 2);
    }
    __syncthreads();

    int p = blockIdx.x * 128 + tid;
    const float* xp = x    + ((size_t)(b * CCH + qtr * 64)) * HWN + p;
    __half*      xh = g_xh + ((size_t)(b * CCH + qtr * 64)) * HWN + p;

    unsigned long long acc2[12];
    #pragma unroll
    for (int m = 0; m < 12; m++) acc2[m] = 0ull;

    #pragma unroll
    for (int cb = 0; cb < 64; cb += 16) {
        float v[16];
        #pragma unroll
        for (int j = 0; j < 16; j++)
            v[j] = xp[(size_t)(cb + j) * HWN];
        #pragma unroll
        for (int j = 0; j < 16; j++)
            xh[(size_t)(cb + j) * HWN] = __float2half_rn(v[j]);
        #pragma unroll
        for (int q = 0; q < 8; q++) {
            P2 xv; xv.f = make_float2(v[q * 2], v[q * 2 + 1]);
            int c2 = (cb >> 1) + q;
            #pragma unroll
            for (int m = 0; m < 12; m++) {
                P2 w; w.f = sW2[m][c2];
                fma2(acc2[m], xv.u, w.u);
            }
        }
    }

    #pragma unroll
    for (int m = 0; m < 12; m++) {
        P2 t; t.u = acc2[m];
        g_part[((size_t)(qtr * 12 + m) * BB + b) * HWN + p] = t.f.x + t.f.y;
    }
}

// ---------------------------------------------------------------------------
// Kernel 1b (flow epilogue): sum 4 partials -> softmax -> dedupe -> compact.
// cnt padded to even (unroll-2 gather in sample).
__global__ __launch_bounds__(128) void DFMAtt_flowepi(
        const float* __restrict__ boff, const float* __restrict__ bwt) {
    int tid = threadIdx.x;
    int b = blockIdx.y;
    int p = blockIdx.x * 128 + tid;

    float acc[12];
    #pragma unroll
    for (int m = 0; m < 12; m++) {
        float q0 = g_part[((size_t)(0 * 12 + m) * BB + b) * HWN + p];
        float q1 = g_part[((size_t)(1 * 12 + m) * BB + b) * HWN + p];
        float q2 = g_part[((size_t)(2 * 12 + m) * BB + b) * HWN + p];
        float q3 = g_part[((size_t)(3 * 12 + m) * BB + b) * HWN + p];
        acc[m] = (q0 + q1) + (q2 + q3);
    }

    float lg[KF];
    #pragma unroll
    for (int k = 0; k < KF; k++) lg[k] = acc[8 + k] + bwt[k];
    float mx = fmaxf(fmaxf(lg[0], lg[1]), fmaxf(lg[2], lg[3]));
    float e[KF], ssum = 0.f;
    #pragma unroll
    for (int k = 0; k < KF; k++) { e[k] = expf(lg[k] - mx); ssum += e[k]; }
    float inv = 1.f / ssum;

    int px = p % WW, py = p / WW;

    int   idxr[16];
    float wtr [16];
    bool  keep[16];
    #pragma unroll
    for (int k = 0; k < KF; k++) {
        float wk = e[k] * inv;
        float fx = acc[k * 2 + 0] + boff[k * 2 + 0];
        float fy = acc[k * 2 + 1] + boff[k * 2 + 1];
        float vx = 2.0f * ((float)px + fx) / (float)(WW - 1) - 1.0f;
        float vy = 2.0f * ((float)py + fy) / (float)(HH - 1) - 1.0f;
        float ix = (vx + 1.0f) * ((float)WW * 0.5f) - 0.5f;
        float iy = (vy + 1.0f) * ((float)HH * 0.5f) - 0.5f;
        float x0f = floorf(ix), y0f = floorf(iy);
        float wx1 = ix - x0f, wx0 = 1.0f - wx1;
        float wy1 = iy - y0f, wy0 = 1.0f - wy1;
        int x0 = (int)x0f, y0 = (int)y0f;
        #pragma unroll
        for (int t = 0; t < 4; t++) {
            int xi = x0 + (t & 1);
            int yi = y0 + (t >> 1);
            float wt = ((t & 1) ? wx1 : wx0) * ((t >> 1) ? wy1 : wy0);
            bool valid = (xi >= 0) && (xi < WW) && (yi >= 0) && (yi < HH);
            int xc = min(max(xi, 0), WW - 1);
            int yc = min(max(yi, 0), HH - 1);
            int q = k * 4 + t;
            idxr[q] = (yc * WW + xc) * OC;
            wtr [q] = valid ? (wk * wt) : 0.0f;
            keep[q] = true;
        }
    }

    #pragma unroll
    for (int j = 1; j < 16; j++)
        #pragma unroll
        for (int i = 0; i < j; i++)
            if (keep[j] && keep[i] && idxr[j] == idxr[i]) {
                wtr[i] += wtr[j];
                keep[j] = false;
            }

    int base = (b * HWN + p) * 16;
    int cnt = 0;
    #pragma unroll
    for (int t = 0; t < 16; t++)
        if (keep[t] && wtr[t] != 0.0f) {
            g_sidx[base + cnt] = idxr[t];
            g_swt [base + cnt] = wtr[t];
            cnt++;
        }
    if (cnt & 1) {                       // pad to even
        g_sidx[base + cnt] = 0;
        g_swt [base + cnt] = 0.0f;
        cnt++;
    }
    g_scnt[b * HWN + p] = cnt;
}

// ---------------------------------------------------------------------------
// Kernel 2: mma.sync fp16 GEMM, CONTINUOUS 4-stage cp.async ring spanning
// tile boundaries (prefetch 3 ahead, wait_group 2). Persistent 296 CTAs.
#define BS_STRIDE 264
#define AS_STRIDE 136
#define B_MAT_BYTES (128 * BS_STRIDE * 2)   // 67584
#define A_STG_BYTES (32 * AS_STRIDE * 2)    // 8704
#define OFF_A B_MAT_BYTES
#define SMEM_TOT (OFF_A + 4 * A_STG_BYTES)  // 102400 -> 2 CTAs/SM

__device__ __forceinline__ void prefA(uint32_t smA, int st, int b, int ck, int prow, int tid) {
    #pragma unroll
    for (int it = 0; it < 2; it++) {
        int idx = tid + it * 256;
        int r = idx >> 4, j = idx & 15;
        const __half* src = g_xh + ((size_t)(b * CCH + ck * 32 + r)) * HWN + prow + j * 8;
        uint32_t dst = smA + (uint32_t)st * A_STG_BYTES + r * (AS_STRIDE * 2) + j * 16;
        CPA16(dst, src);
    }
}

__global__ __launch_bounds__(256, 2) void DFMAtt_gemm_mma(const float* __restrict__ bc) {
    extern __shared__ unsigned char sm[];
    uint32_t sb = smem_u32(sm);
    int tid = threadIdx.x, wid = tid >> 5, lane = tid & 31;
    int nh = (blockIdx.x >= 148) ? 1 : 0;
    int local = blockIdx.x % 148;

    for (int idx = tid; idx < 128 * 32; idx += 256) {
        int r = idx >> 5, j = idx & 31;
        const __half* wsrc = g_wh + (size_t)(nh * 128 + r) * CCH + j * 8;
        *(uint4*)(sm + r * (BS_STRIDE * 2) + j * 16) = *(const uint4*)wsrc;
    }

    int wm = wid >> 2, wn = wid & 3;
    int p0w = wm * 64, o0w = wn * 32;
    int grp = lane >> 3, lr = lane & 7;

    int a_dc = ((grp >> 1) << 3) + lr;
    int a_dp = (grp & 1) << 3;
    uint32_t aoff[4];
    #pragma unroll
    for (int i = 0; i < 4; i++)
        aoff[i] = (uint32_t)(a_dc * (AS_STRIDE * 2) + (p0w + i * 16 + a_dp) * 2);
    int b_dr = ((grp >> 1) << 3) + lr;
    int b_dk = (grp & 1) << 4;
    uint32_t boff[2];
    #pragma unroll
    for (int t = 0; t < 2; t++)
        boff[t] = (uint32_t)((o0w + t * 16 + b_dr) * (BS_STRIDE * 2) + b_dk);

    uint32_t smA = sb + OFF_A;

    int row = lane >> 2, col2 = (lane & 3) * 2;
    float2 biasv[4];
    #pragma unroll
    for (int nt = 0; nt < 4; nt++)
        biasv[nt] = *(const float2*)&bc[nh * 128 + o0w + nt * 8 + col2];

    int T = (576 - local + 147) / 148;
    int bb = local / 72, pr = local % 72;

    prefA(smA, 0, bb, 0, pr * 128, tid); CPA_COMMIT();
    prefA(smA, 1, bb, 1, pr * 128, tid); CPA_COMMIT();
    prefA(smA, 2, bb, 2, pr * 128, tid); CPA_COMMIT();

    int g = 0;
    for (int ti = 0; ti < T; ti++) {
        int b = bb, prow = pr * 128;
        int bbN = bb + 2, prN = pr + 4;
        if (prN >= 72) { prN -= 72; bbN++; }

        float acc[4][4][4];
        #pragma unroll
        for (int i = 0; i < 4; i++)
            #pragma unroll
            for (int nt = 0; nt < 4; nt++)
                #pragma unroll
                for (int q = 0; q < 4; q++) acc[i][nt][q] = 0.f;

        #pragma unroll 1
        for (int ck = 0; ck < 8; ck++, g++) {
            CPA_WAIT2();
            __syncthreads();
            uint32_t Ab = smA + (uint32_t)(g & 3) * A_STG_BYTES;

            #pragma unroll
            for (int ks = 0; ks < 2; ks++) {
                uint32_t ac  = (uint32_t)(ks * 16 * (AS_STRIDE * 2));
                uint32_t bcf = (uint32_t)((ck * 32 + ks * 16) * 2);
                uint32_t ah[4][4];
                #pragma unroll
                for (int i = 0; i < 4; i++) LDSM_X4_T(ah[i], Ab + ac + aoff[i]);
                uint32_t bh[2][4];
                #pragma unroll
                for (int t = 0; t < 2; t++) LDSM_X4(bh[t], sb + bcf + boff[t]);
                #pragma unroll
                for (int i = 0; i < 4; i++)
                    #pragma unroll
                    for (int nt = 0; nt < 4; nt++)
                        mma16816(acc[i][nt], ah[i], &bh[nt >> 1][(nt & 1) * 2]);
            }

            int gp = g + 3;
            if (gp < T * 8) {
                if (ck < 5) prefA(smA, gp & 3, b,   (ck + 3),     prow,      tid);
                else        prefA(smA, gp & 3, bbN, (ck + 3) & 7, prN * 128, tid);
            }
            CPA_COMMIT();
        }

        #pragma unroll
        for (int i = 0; i < 4; i++) {
            int p = prow + p0w + i * 16 + row;
            __half* dst0 = g_projh + ((size_t)b * HWN + p) * OC + nh * 128 + o0w + col2;
            #pragma unroll
            for (int nt = 0; nt < 4; nt++) {
                __half2 v0 = __floats2half2_rn(acc[i][nt][0] + biasv[nt].x,
                                               acc[i][nt][1] + biasv[nt].y);
                __half2 v1 = __floats2half2_rn(acc[i][nt][2] + biasv[nt].x,
                                               acc[i][nt][3] + biasv[nt].y);
                *(__half2*)(dst0 + nt * 8)          = v0;
                *(__half2*)(dst0 + nt * 8 + 8 * OC) = v1;
            }
        }
        bb = bbN; pr = prN;
    }
}

// ---------------------------------------------------------------------------
// Kernel 3: out[b][o][p] = sum_{i<cnt} w_i * projh[b][idx_i][o]
// unroll-2 gather; half2 staging smem (16.5KB) + launch_bounds(256,8) for
// 8 blocks/SM. Staging layout: col = lane + k*32 holds channels
// (lane*8 + k*2, +1); row stride 129 half2 -> conflict-free both phases.
__global__ __launch_bounds__(256, 8) void DFMAtt_sample(float* __restrict__ out) {
    __shared__ __half2 s_acc[32][129];
    __shared__ int     s_idx[32][16];
    __shared__ float   s_wt [32][16];
    __shared__ int     s_cnt[32];

    int b  = blockIdx.y;
    int p0 = blockIdx.x * 32;
    int tid = threadIdx.x;

    {
        const int*   gi = g_sidx + (b * HWN + p0) * 16;
        const float* gw = g_swt  + (b * HWN + p0) * 16;
        for (int i = tid; i < 512; i += 256) {
            s_idx[i >> 4][i & 15] = gi[i];
            s_wt [i >> 4][i & 15] = gw[i];
        }
        if (tid < 32) s_cnt[tid] = g_scnt[b * HWN + p0 + tid];
    }
    __syncthreads();

    const __half* projb = g_projh + (size_t)b * HWN * OC;
    int lane = tid & 31;
    int pg   = tid >> 5;

    #pragma unroll 1
    for (int s = 0; s < 4; s++) {
        int pi = s * 8 + pg;
        int cnt = s_cnt[pi];
        const __half* pb = projb + lane * 8;
        float f0 = 0.f, f1 = 0.f, f2 = 0.f, f3 = 0.f;
        float f4 = 0.f, f5 = 0.f, f6 = 0.f, f7 = 0.f;
        #pragma unroll 1
        for (int i = 0; i < cnt; i += 2) {
            float w0 = s_wt[pi][i];
            float w1 = s_wt[pi][i + 1];
            uint4 r0 = *(const uint4*)(pb + s_idx[pi][i]);
            uint4 r1 = *(const uint4*)(pb + s_idx[pi][i + 1]);
            {
                float2 a0 = __half22float2(*(__half2*)&r0.x);
                float2 a1 = __half22float2(*(__half2*)&r0.y);
                float2 a2 = __half22float2(*(__half2*)&r0.z);
                float2 a3 = __half22float2(*(__half2*)&r0.w);
                f0 = fmaf(w0, a0.x, f0); f1 = fmaf(w0, a0.y, f1);
                f2 = fmaf(w0, a1.x, f2); f3 = fmaf(w0, a1.y, f3);
                f4 = fmaf(w0, a2.x, f4); f5 = fmaf(w0, a2.y, f5);
                f6 = fmaf(w0, a3.x, f6); f7 = fmaf(w0, a3.y, f7);
            }
            {
                float2 a0 = __half22float2(*(__half2*)&r1.x);
                float2 a1 = __half22float2(*(__half2*)&r1.y);
                float2 a2 = __half22float2(*(__half2*)&r1.z);
                float2 a3 = __half22float2(*(__half2*)&r1.w);
                f0 = fmaf(w1, a0.x, f0); f1 = fmaf(w1, a0.y, f1);
                f2 = fmaf(w1, a1.x, f2); f3 = fmaf(w1, a1.y, f3);
                f4 = fmaf(w1, a2.x, f4); f5 = fmaf(w1, a2.y, f5);
                f6 = fmaf(w1, a3.x, f6); f7 = fmaf(w1, a3.y, f7);
            }
        }
        // col = lane + k*32 : consecutive per k-store -> conflict-free
        s_acc[pi][lane      ] = __floats2half2_rn(f0, f1);
        s_acc[pi][lane + 32 ] = __floats2half2_rn(f2, f3);
        s_acc[pi][lane + 64 ] = __floats2half2_rn(f4, f5);
        s_acc[pi][lane + 96 ] = __floats2half2_rn(f6, f7);
    }
    __syncthreads();

    // write phase: op = col index; channels o = (op&31)*8 + (op>>5)*2, o+1
    float* ob = out + (size_t)b * OC * HWN + p0;
    int orow = tid >> 5;     // 0..7
    int pi   = tid & 31;
    #pragma unroll 1
    for (int j = 0; j < 16; j++) {
        int op = orow + j * 8;                  // 0..127
        int o  = (op & 31) * 8 + (op >> 5) * 2;
        float2 f = __half22float2(s_acc[pi][op]);
        ob[(size_t)o * HWN + pi]       = f.x;
        ob[(size_t)(o + 1) * HWN + pi] = f.y;
    }
}

// ---------------------------------------------------------------------------
extern "C" void kernel_launch(void* const* d_in, const int* in_sizes, int n_in,
                              void* d_out, int out_size) {
    const float* x    = (const float*)d_in[0];
    const float* Wc   = (const float*)d_in[1];
    const float* bc   = (const float*)d_in[2];
    const float* Woff = (const float*)d_in[3];
    const float* boff = (const float*)d_in[4];
    const float* Wwt  = (const float*)d_in[5];
    const float* bwt  = (const float*)d_in[6];
    float* out = (float*)d_out;

    cudaFuncSetAttribute(DFMAtt_gemm_mma,
                         cudaFuncAttributeMaxDynamicSharedMemorySize, SMEM_TOT);

    dim3 gd(72, BB, 4);
    DFMAtt_dots<<<gd, 128>>>(x, Wc, Woff, Wwt);

    dim3 ge(72, BB);
    DFMAtt_flowepi<<<ge, 128>>>(boff, bwt);

    DFMAtt_gemm_mma<<<296, 256, SMEM_TOT>>>(bc);

    dim3 gs(HWN / 32, BB);
    DFMAtt_sample<<<gs, 256>>>(out);
}